// round 13
// baseline (speedup 1.0000x reference)
#include <cuda_runtime.h>

#define NN 768
#define FD 64
#define DE 32
#define HD 64
#define H2 128
#define EGRID 444
#define PGRID 48

typedef unsigned long long u64;

// Scratch (allocation-free rule: __device__ globals), 16B-aligned
__device__ __align__(16) float g_P [NN * HD];
__device__ __align__(16) float g_Q [NN * HD];
__device__ __align__(16) float g_X1[NN * HD];
__device__ __align__(16) float g_X2[NN * HD];
__device__ unsigned g_cnt;          // zero-init at load; reset by final_kernel
__device__ unsigned g_edges[NN * NN];

// ---- packed f32x2 helpers (sm_103a) ----
__device__ __forceinline__ u64 pack2(float lo, float hi) {
    u64 r; asm("mov.b64 %0, {%1, %2};" : "=l"(r) : "f"(lo), "f"(hi)); return r;
}
__device__ __forceinline__ void unpack2(u64 v, float& lo, float& hi) {
    asm("mov.b64 {%0, %1}, %2;" : "=f"(lo), "=f"(hi) : "l"(v));
}
__device__ __forceinline__ u64 ffma2(u64 a, u64 b, u64 c) {
    u64 d; asm("fma.rn.f32x2 %0, %1, %2, %3;" : "=l"(d) : "l"(a), "l"(b), "l"(c));
    return d;
}
__device__ __forceinline__ u64 fadd2(u64 a, u64 b) {
    u64 d; asm("add.rn.f32x2 %0, %1, %2;" : "=l"(d) : "l"(a), "l"(b)); return d;
}
__device__ __forceinline__ u64 relu2(u64 v) {
    float lo, hi; unpack2(v, lo, hi);
    return pack2(fmaxf(lo, 0.f), fmaxf(hi, 0.f));
}

// Fused prep: 16 nodes per block (W staged once per 16 nodes), optional
// adjacency compaction, P/Q GEMMs, and zeroing of the next accumulator.
__global__ __launch_bounds__(256) void prep_kernel(
    const float* __restrict__ A,   // null => skip compaction
    const float* __restrict__ x, const float* __restrict__ W,
    const float* __restrict__ ba, float* __restrict__ P,
    float* __restrict__ Q, float* __restrict__ Xz)
{
    __shared__ float sW[2 * FD * HD];   // 32 KB
    __shared__ float sx[16 * FD];       // 4 KB
    __shared__ float sba[HD];
    __shared__ unsigned lcnt[4], lbase[4];

    const int tid = threadIdx.x;
    const int b   = blockIdx.x;

    // zero accumulator slice: 48 blocks x 256 threads x 1 float4 = NN*HD
    ((float4*)Xz)[b * 256 + tid] = make_float4(0.f, 0.f, 0.f, 0.f);

#pragma unroll
    for (int k = 0; k < 8; k++)
        ((float4*)sW)[tid + k * 256] = ((const float4*)W)[tid + k * 256];
    ((float4*)sx)[tid] = ((const float4*)(x + b * 16 * FD))[tid];
    if (tid < HD) sba[tid] = ba[tid];
    __syncthreads();

    // compaction: 16 rows in 4 groups of 4
    if (A) {
        for (int g = 0; g < 4; g++) {
            if (tid < 4) lcnt[tid] = 0;
            __syncthreads();
            unsigned myj[4][3]; int mc[4]; unsigned mpos[4];
#pragma unroll
            for (int r = 0; r < 4; r++) {
                mc[r] = 0;
                const int row = b * 16 + g * 4 + r;
                const float* Ar = A + (size_t)row * NN;
#pragma unroll
                for (int t = 0; t < 3; t++) {
                    int j = tid + t * 256;
                    if (Ar[j] != 0.0f) myj[r][mc[r]++] = (unsigned)j;
                }
                mpos[r] = mc[r] ? atomicAdd(&lcnt[r], (unsigned)mc[r]) : 0u;
            }
            __syncthreads();
            if (tid == 0) {
#pragma unroll
                for (int r = 0; r < 4; r++)
                    lbase[r] = atomicAdd(&g_cnt, lcnt[r]);
            }
            __syncthreads();
#pragma unroll
            for (int r = 0; r < 4; r++) {
                const int row = b * 16 + g * 4 + r;
                unsigned base = lbase[r] + mpos[r];
                unsigned rowbits = (unsigned)row << 10;
                for (int t = 0; t < mc[r]; t++)
                    g_edges[base + t] = rowbits | myj[r][t];
            }
            __syncthreads();   // lcnt reused next group
        }
    }

    // pq compute for 16 nodes (4 rounds of 4)
    const int nl = tid >> 6;
    const int h  = tid & 63;
#pragma unroll
    for (int s = 0; s < 4; s++) {
        const int nloc = s * 4 + nl;
        const int node = b * 16 + nloc;
        float p = sba[h], q = 0.f;
#pragma unroll
        for (int f = 0; f < FD; f++) {
            float xv = sx[nloc * FD + f];
            float wi = sW[f * HD + h];
            float wd = sW[(FD + f) * HD + h];
            p = fmaf(xv, wi - wd, p);
            q = fmaf(xv, wd, q);
        }
        P[node * HD + h] = p;
        Q[node * HD + h] = q;
    }
}

// Warp-pair per 32-edge batch; both layers in the 4-edge x 8-h lane tile.
// e-staging tile ALIASES the warp's own half of the pair z-tile (es is fully
// consumed by layer-a before z overwrites it). 3 CTAs/SM via reduced smem+regs.
__global__ __launch_bounds__(256, 3) void edge_kernel(
    const float* __restrict__ e,  const float* __restrict__ P,
    const float* __restrict__ Q,  const float* __restrict__ W,
    const float* __restrict__ Wb, const float* __restrict__ bb,
    float* __restrict__ out)
{
    extern __shared__ float sm[];
    float* sWe = sm;               // 2048
    float* sWb = sm + 2048;        // 4096
    float* sbb = sm + 6144;        // 64
    float* zx  = sm + 6208;        // 4 pairs * [64][32] = 8192
    // total 14400 floats = 57600 B

    const int tid  = threadIdx.x;
    const int lane = tid & 31;
    const int warp = tid >> 5;
    const int pib  = warp >> 1;        // pair in block (0..3)
    const int hh   = warp & 1;         // h-half
    const int hbase = hh * 32;
    const int barid = 1 + pib;
    const int eg   = lane >> 2;        // edge group of 4 (0..7)
    const int hg   = lane & 3;         // h group of 8 / own edge slot
    const int hoff = hbase + hg * 8;

    const unsigned cnt  = g_cnt;
    const unsigned nbat = (cnt + 31u) >> 5;
    const unsigned pairG  = (unsigned)pib * gridDim.x + blockIdx.x;
    const unsigned npairs = gridDim.x * 4u;
    float* zs = zx + pib * (HD * 32);   // [k][edge] pair tile
    float* es = zs + hbase * 32;        // own warp's 32 rows, [de][edge]

    // ---- prefetch first batch: edges + P/Q only (overlaps weight staging) ----
    unsigned bat = pairG;
    bool have = bat < nbat;
    u64 pq2[16];         // becomes layer-a accumulator (4e x 8h, h-packed)
    int iarr[4];
    int jown = 0;
    if (have) {
        const unsigned ebase = bat * 32u + (unsigned)(eg * 4);
        uint4 pks = *(const uint4*)(g_edges + ebase);
        unsigned pkarr[4] = {pks.x, pks.y, pks.z, pks.w};
#pragma unroll
        for (int e4 = 0; e4 < 4; e4++) {
            int ii = min((int)(pkarr[e4] >> 10), NN - 1);
            int jj = min((int)(pkarr[e4] & 1023u), NN - 1);
            iarr[e4] = ii;
            if (e4 == hg) jown = jj;
            const ulonglong2* Pp = (const ulonglong2*)(P + ii * HD + hoff);
            const ulonglong2* Qp = (const ulonglong2*)(Q + jj * HD + hoff);
            ulonglong2 p0 = Pp[0], p1 = Pp[1], q0 = Qp[0], q1 = Qp[1];
            pq2[e4 * 4 + 0] = fadd2(p0.x, q0.x);
            pq2[e4 * 4 + 1] = fadd2(p0.y, q0.y);
            pq2[e4 * 4 + 2] = fadd2(p1.x, q1.x);
            pq2[e4 * 4 + 3] = fadd2(p1.y, q1.y);
        }
    }

    // ---- weight staging ----
    {
        const float4* Wg = (const float4*)(W + (2 * FD) * HD);
        ((float4*)sWe)[tid]       = Wg[tid];
        ((float4*)sWe)[tid + 256] = Wg[tid + 256];
        const float4* Wbg = (const float4*)Wb;
#pragma unroll
        for (int k = 0; k < 4; k++)
            ((float4*)sWb)[tid + k * 256] = Wbg[tid + k * 256];
        if (tid < HD) sbb[tid] = bb[tid];
    }
    __syncthreads();

    while (have) {
        // stage own edge's e-row into es[de][edge=lane] (transient regs only)
        {
            const float4* epp = (const float4*)(e + (size_t)(iarr[hg] * NN + jown) * DE);
#pragma unroll
            for (int q4 = 0; q4 < 8; q4++) {
                float4 v = epp[q4];
                es[(q4 * 4 + 0) * 32 + lane] = v.x;
                es[(q4 * 4 + 1) * 32 + lane] = v.y;
                es[(q4 * 4 + 2) * 32 + lane] = v.z;
                es[(q4 * 4 + 3) * 32 + lane] = v.w;
            }
        }
        __syncwarp();

        // ---- layer a in the tile (accumulate into pq2 in place) ----
        u64* z2t = pq2;
#pragma unroll
        for (int de = 0; de < DE; de++) {
            float4 e4v = *(const float4*)(es + de * 32 + eg * 4);
            const ulonglong2* wp = (const ulonglong2*)(sWe + de * HD + hoff);
            ulonglong2 wA = wp[0], wB = wp[1];
            u64 zd;
            zd = pack2(e4v.x, e4v.x);
            z2t[0]  = ffma2(zd, wA.x, z2t[0]);  z2t[1]  = ffma2(zd, wA.y, z2t[1]);
            z2t[2]  = ffma2(zd, wB.x, z2t[2]);  z2t[3]  = ffma2(zd, wB.y, z2t[3]);
            zd = pack2(e4v.y, e4v.y);
            z2t[4]  = ffma2(zd, wA.x, z2t[4]);  z2t[5]  = ffma2(zd, wA.y, z2t[5]);
            z2t[6]  = ffma2(zd, wB.x, z2t[6]);  z2t[7]  = ffma2(zd, wB.y, z2t[7]);
            zd = pack2(e4v.z, e4v.z);
            z2t[8]  = ffma2(zd, wA.x, z2t[8]);  z2t[9]  = ffma2(zd, wA.y, z2t[9]);
            z2t[10] = ffma2(zd, wB.x, z2t[10]); z2t[11] = ffma2(zd, wB.y, z2t[11]);
            zd = pack2(e4v.w, e4v.w);
            z2t[12] = ffma2(zd, wA.x, z2t[12]); z2t[13] = ffma2(zd, wA.y, z2t[13]);
            z2t[14] = ffma2(zd, wB.x, z2t[14]); z2t[15] = ffma2(zd, wB.y, z2t[15]);
        }
        __syncwarp();   // all lanes done reading es before z overwrites it

        // relu + stage z to pair tile [k][edge] (own rows overwrite es)
#pragma unroll
        for (int e4 = 0; e4 < 4; e4++) {
#pragma unroll
            for (int c = 0; c < 4; c++) {
                float lo, hi; unpack2(z2t[e4 * 4 + c], lo, hi);
                zs[(hoff + 2 * c + 0) * 32 + eg * 4 + e4] = fmaxf(lo, 0.f);
                zs[(hoff + 2 * c + 1) * 32 + eg * 4 + e4] = fmaxf(hi, 0.f);
            }
        }
        asm volatile("bar.sync %0, 64;" :: "r"(barid) : "memory");

        // ---- layer b (4 edges x 8 h tile) ----
        u64 m2[16];
        {
            const ulonglong2* bp = (const ulonglong2*)(sbb + hoff);
            ulonglong2 b0 = bp[0], b1 = bp[1];
#pragma unroll
            for (int e4 = 0; e4 < 4; e4++) {
                m2[e4 * 4 + 0] = b0.x; m2[e4 * 4 + 1] = b0.y;
                m2[e4 * 4 + 2] = b1.x; m2[e4 * 4 + 3] = b1.y;
            }
        }
#pragma unroll 8
        for (int k = 0; k < HD; k++) {
            float4 z4 = *(const float4*)(zs + k * 32 + eg * 4);
            const ulonglong2* wp = (const ulonglong2*)(sWb + k * HD + hoff);
            ulonglong2 wA = wp[0], wB = wp[1];
            u64 zd;
            zd = pack2(z4.x, z4.x);
            m2[0]  = ffma2(zd, wA.x, m2[0]);  m2[1]  = ffma2(zd, wA.y, m2[1]);
            m2[2]  = ffma2(zd, wB.x, m2[2]);  m2[3]  = ffma2(zd, wB.y, m2[3]);
            zd = pack2(z4.y, z4.y);
            m2[4]  = ffma2(zd, wA.x, m2[4]);  m2[5]  = ffma2(zd, wA.y, m2[5]);
            m2[6]  = ffma2(zd, wB.x, m2[6]);  m2[7]  = ffma2(zd, wB.y, m2[7]);
            zd = pack2(z4.z, z4.z);
            m2[8]  = ffma2(zd, wA.x, m2[8]);  m2[9]  = ffma2(zd, wA.y, m2[9]);
            m2[10] = ffma2(zd, wB.x, m2[10]); m2[11] = ffma2(zd, wB.y, m2[11]);
            zd = pack2(z4.w, z4.w);
            m2[12] = ffma2(zd, wA.x, m2[12]); m2[13] = ffma2(zd, wA.y, m2[13]);
            m2[14] = ffma2(zd, wB.x, m2[14]); m2[15] = ffma2(zd, wB.y, m2[15]);
        }

        // relu + scatter (fused when 4 edges share row i)
#pragma unroll
        for (int c = 0; c < 16; c++) m2[c] = relu2(m2[c]);

        const unsigned ebase = bat * 32u + (unsigned)(eg * 4);
        const bool fuse = (iarr[0] == iarr[1]) & (iarr[1] == iarr[2]) &
                          (iarr[2] == iarr[3]) & (ebase + 3u < cnt);
        if (fuse) {
            float4* op = (float4*)(out + iarr[0] * HD + hoff);
#pragma unroll
            for (int c = 0; c < 4; c++)
                m2[c] = fadd2(fadd2(m2[c], m2[4 + c]), fadd2(m2[8 + c], m2[12 + c]));
            float a0, a1, a2, a3;
            unpack2(m2[0], a0, a1); unpack2(m2[1], a2, a3);
            atomicAdd(op,     make_float4(a0, a1, a2, a3));
            unpack2(m2[2], a0, a1); unpack2(m2[3], a2, a3);
            atomicAdd(op + 1, make_float4(a0, a1, a2, a3));
        } else {
#pragma unroll
            for (int e4 = 0; e4 < 4; e4++) {
                if (ebase + (unsigned)e4 < cnt) {
                    float4* op = (float4*)(out + iarr[e4] * HD + hoff);
                    float a0, a1, a2, a3;
                    unpack2(m2[e4 * 4 + 0], a0, a1);
                    unpack2(m2[e4 * 4 + 1], a2, a3);
                    atomicAdd(op,     make_float4(a0, a1, a2, a3));
                    unpack2(m2[e4 * 4 + 2], a0, a1);
                    unpack2(m2[e4 * 4 + 3], a2, a3);
                    atomicAdd(op + 1, make_float4(a0, a1, a2, a3));
                }
            }
        }

        // ---- advance (rare: >1 task per pair) ----
        bat += npairs;
        have = bat < nbat;
        if (have) {
            asm volatile("bar.sync %0, 64;" :: "r"(barid) : "memory");
            const unsigned eb2 = bat * 32u + (unsigned)(eg * 4);
            uint4 pks = *(const uint4*)(g_edges + eb2);
            unsigned pkarr[4] = {pks.x, pks.y, pks.z, pks.w};
#pragma unroll
            for (int e4 = 0; e4 < 4; e4++) {
                int ii = min((int)(pkarr[e4] >> 10), NN - 1);
                int jj = min((int)(pkarr[e4] & 1023u), NN - 1);
                iarr[e4] = ii;
                if (e4 == hg) jown = jj;
                const ulonglong2* Pp = (const ulonglong2*)(P + ii * HD + hoff);
                const ulonglong2* Qp = (const ulonglong2*)(Q + jj * HD + hoff);
                ulonglong2 p0 = Pp[0], p1 = Pp[1], q0 = Qp[0], q1 = Qp[1];
                pq2[e4 * 4 + 0] = fadd2(p0.x, q0.x);
                pq2[e4 * 4 + 1] = fadd2(p0.y, q0.y);
                pq2[e4 * 4 + 2] = fadd2(p1.x, q1.x);
                pq2[e4 * 4 + 3] = fadd2(p1.y, q1.y);
            }
        }
    }
}

// out[i] = sigmoid( relu(x2_i @ W3 + b3) @ W4 + b4 ); resets g_cnt (runs last).
__global__ __launch_bounds__(128) void final_kernel(
    const float* __restrict__ x,
    const float* __restrict__ W3, const float* __restrict__ b3,
    const float* __restrict__ W4, const float* __restrict__ b4,
    float* __restrict__ out)
{
    __shared__ float sx[HD];
    __shared__ float sred[H2];
    const int i = blockIdx.x, t = threadIdx.x;
    if (i == 0 && t == 0) g_cnt = 0;
    if (t < HD) sx[t] = x[i * HD + t];
    __syncthreads();

    float h = b3[t];
#pragma unroll
    for (int k = 0; k < HD; k++)
        h = fmaf(sx[k], W3[k * H2 + t], h);
    h = fmaxf(h, 0.f);

    sred[t] = h * W4[t];
    __syncthreads();
#pragma unroll
    for (int s = 64; s > 0; s >>= 1) {
        if (t < s) sred[t] += sred[t + s];
        __syncthreads();
    }
    if (t == 0) {
        float v = sred[0] + b4[0];
        out[i] = 1.0f / (1.0f + expf(-v));
    }
}

extern "C" void kernel_launch(void* const* d_in, const int* in_sizes, int n_in,
                              void* d_out, int out_size)
{
    const float* A   = (const float*)d_in[0];
    const float* x   = (const float*)d_in[1];
    const float* e   = (const float*)d_in[2];
    const float* W1a = (const float*)d_in[3];
    const float* b1a = (const float*)d_in[4];
    const float* W1b = (const float*)d_in[5];
    const float* b1b = (const float*)d_in[6];
    const float* W2a = (const float*)d_in[7];
    const float* b2a = (const float*)d_in[8];
    const float* W2b = (const float*)d_in[9];
    const float* b2b = (const float*)d_in[10];
    const float* W3  = (const float*)d_in[11];
    const float* b3  = (const float*)d_in[12];
    const float* W4  = (const float*)d_in[13];
    const float* b4  = (const float*)d_in[14];
    float* out = (float*)d_out;

    float *P, *Q, *X1, *X2;
    cudaGetSymbolAddress((void**)&P,  g_P);
    cudaGetSymbolAddress((void**)&Q,  g_Q);
    cudaGetSymbolAddress((void**)&X1, g_X1);
    cudaGetSymbolAddress((void**)&X2, g_X2);

    const int SMEM = (2048 + 4096 + 64 + 4 * HD * 32) * 4;   // 57600 B
    cudaFuncSetAttribute(edge_kernel, cudaFuncAttributeMaxDynamicSharedMemorySize, SMEM);

    // Layer 1 (prep compacts A, computes P/Q, zeroes X1)
    prep_kernel<<<PGRID, 256>>>(A, x, W1a, b1a, P, Q, X1);
    edge_kernel<<<EGRID, 256, SMEM>>>(e, P, Q, W1a, W1b, b1b, X1);
    // Layer 2 (no recompaction)
    prep_kernel<<<PGRID, 256>>>(nullptr, X1, W2a, b2a, P, Q, X2);
    edge_kernel<<<EGRID, 256, SMEM>>>(e, P, Q, W2a, W2b, b2b, X2);
    // Head (also resets g_cnt)
    final_kernel<<<NN, H2>>>(X2, W3, b3, W4, b4, out);
}

// round 14
// speedup vs baseline: 1.2412x; 1.2412x over previous
#include <cuda_runtime.h>

#define NN 768
#define FD 64
#define DE 32
#define HD 64
#define H2 128
#define EGRID 444

typedef unsigned long long u64;

// Scratch (allocation-free rule: __device__ globals), 16B-aligned
__device__ __align__(16) float g_P [NN * HD];
__device__ __align__(16) float g_Q [NN * HD];
__device__ __align__(16) float g_X1[NN * HD];
__device__ __align__(16) float g_X2[NN * HD];
__device__ unsigned g_cnt;          // zero-init at load; reset by final_kernel
__device__ unsigned g_edges[NN * NN];

// ---- packed f32x2 helpers (sm_103a) ----
__device__ __forceinline__ u64 pack2(float lo, float hi) {
    u64 r; asm("mov.b64 %0, {%1, %2};" : "=l"(r) : "f"(lo), "f"(hi)); return r;
}
__device__ __forceinline__ void unpack2(u64 v, float& lo, float& hi) {
    asm("mov.b64 {%0, %1}, %2;" : "=f"(lo), "=f"(hi) : "l"(v));
}
__device__ __forceinline__ u64 ffma2(u64 a, u64 b, u64 c) {
    u64 d; asm("fma.rn.f32x2 %0, %1, %2, %3;" : "=l"(d) : "l"(a), "l"(b), "l"(c));
    return d;
}
__device__ __forceinline__ u64 fadd2(u64 a, u64 b) {
    u64 d; asm("add.rn.f32x2 %0, %1, %2;" : "=l"(d) : "l"(a), "l"(b)); return d;
}
__device__ __forceinline__ u64 relu2(u64 v) {
    float lo, hi; unpack2(v, lo, hi);
    return pack2(fmaxf(lo, 0.f), fmaxf(hi, 0.f));
}

// Fused prep (R12-proven): optional compaction + P/Q GEMMs + zero accumulator.
__global__ __launch_bounds__(256) void prep_kernel(
    const float* __restrict__ A,   // null => skip compaction
    const float* __restrict__ x, const float* __restrict__ W,
    const float* __restrict__ ba, float* __restrict__ P,
    float* __restrict__ Q, float* __restrict__ Xz)
{
    __shared__ float sW[2 * FD * HD];   // 32 KB
    __shared__ float sx[4][FD];
    __shared__ unsigned lcnt[4], lbase[4];

    const int tid = threadIdx.x;
    const int b   = blockIdx.x;
    const int nl  = tid >> 6;
    const int h   = tid & 63;
    const int node = b * 4 + nl;

    {
        unsigned g = b * 256u + (unsigned)tid;
        if (g < (NN * HD) / 4) ((float4*)Xz)[g] = make_float4(0.f, 0.f, 0.f, 0.f);
    }

    if (tid < 4) lcnt[tid] = 0;
#pragma unroll
    for (int k = 0; k < 8; k++)
        ((float4*)sW)[tid + k * 256] = ((const float4*)W)[tid + k * 256];
    sx[nl][h] = x[node * FD + h];
    __syncthreads();

    unsigned myj[4][3]; int mc[4]; unsigned mpos[4];
    if (A) {
#pragma unroll
        for (int r = 0; r < 4; r++) {
            mc[r] = 0;
            const float* Ar = A + (size_t)(b * 4 + r) * NN;
#pragma unroll
            for (int t = 0; t < 3; t++) {
                int j = tid + t * 256;
                if (Ar[j] != 0.0f) myj[r][mc[r]++] = (unsigned)j;
            }
            mpos[r] = mc[r] ? atomicAdd(&lcnt[r], (unsigned)mc[r]) : 0u;
        }
    }

    float p = ba[h], q = 0.f;
#pragma unroll
    for (int f = 0; f < FD; f++) {
        float xv = sx[nl][f];
        float wi = sW[f * HD + h];
        float wd = sW[(FD + f) * HD + h];
        p = fmaf(xv, wi - wd, p);
        q = fmaf(xv, wd, q);
    }
    P[node * HD + h] = p;
    Q[node * HD + h] = q;

    if (A) {
        __syncthreads();
        if (tid == 0) {
#pragma unroll
            for (int r = 0; r < 4; r++)
                lbase[r] = atomicAdd(&g_cnt, lcnt[r]);
        }
        __syncthreads();
#pragma unroll
        for (int r = 0; r < 4; r++) {
            unsigned base = lbase[r] + mpos[r];
            unsigned rowbits = (unsigned)(b * 4 + r) << 10;
            for (int t = 0; t < mc[r]; t++)
                g_edges[base + t] = rowbits | myj[r][t];
        }
    }
}

// Warp-QUAD per 32-edge batch: 4 warps, each owning a 16-wide h-quarter;
// lane tile = 4 edges x 4 h. Halves per-warp critical path vs the pair
// design; 888 quads (grid 444, 3 CTAs/SM) ~= 922 tasks, all warps busy.
__global__ __launch_bounds__(256, 3) void edge_kernel(
    const float* __restrict__ e,  const float* __restrict__ P,
    const float* __restrict__ Q,  const float* __restrict__ W,
    const float* __restrict__ Wb, const float* __restrict__ bb,
    float* __restrict__ out)
{
    extern __shared__ float sm[];
    float* sWe = sm;               // 2048
    float* sWb = sm + 2048;        // 4096
    float* sbb = sm + 6144;        // 64
    float* qbuf = sm + 6208;       // 2 quads * (zs 2048 u64-floats + es 1024)
    // total 12352 floats = 49408 B

    const int tid  = threadIdx.x;
    const int lane = tid & 31;
    const int warp = tid >> 5;
    const int qib  = warp >> 2;        // quad in block (0..1)
    const int wq   = warp & 3;         // h-quarter (16 h each)
    const int barid = 1 + qib;
    const int eg   = lane >> 2;        // edge group of 4 (0..7)
    const int hg   = lane & 3;
    const int hoff = wq * 16 + hg * 4; // this lane's 4 h dims
    // staging ownership: edge 8*wq + (lane&7), de-chunk (lane>>3)*8
    const int sedge = 8 * wq + (lane & 7);
    const int sde   = (lane >> 3) * 8;

    const unsigned cnt  = g_cnt;
    const unsigned nbat = (cnt + 31u) >> 5;
    const unsigned quadG  = (unsigned)qib * gridDim.x + blockIdx.x;
    const unsigned nquads = gridDim.x * 2u;
    u64*   zsu = (u64*)(qbuf + qib * 3072);        // [32 k2][32 edge] u64
    float* es  = qbuf + qib * 3072 + 2048;         // [32 de][32 edge] float

    // ---- prefetch first batch (overlaps weight staging) ----
    unsigned bat = quadG;
    bool have = bat < nbat;
    u64 pq2[8];          // tile accumulator: [4 edges][2 packed h-pairs]
    float er[8];         // staged e chunk (own sedge, de sde..sde+7)
    int iarr[4];
    if (have) {
        const unsigned ebase = bat * 32u + (unsigned)(eg * 4);
        uint4 pks = *(const uint4*)(g_edges + ebase);
        unsigned pkarr[4] = {pks.x, pks.y, pks.z, pks.w};
#pragma unroll
        for (int e4 = 0; e4 < 4; e4++) {
            int ii = min((int)(pkarr[e4] >> 10), NN - 1);
            int jj = min((int)(pkarr[e4] & 1023u), NN - 1);
            iarr[e4] = ii;
            ulonglong2 pv = *(const ulonglong2*)(P + ii * HD + hoff);
            ulonglong2 qv = *(const ulonglong2*)(Q + jj * HD + hoff);
            pq2[e4 * 2 + 0] = fadd2(pv.x, qv.x);
            pq2[e4 * 2 + 1] = fadd2(pv.y, qv.y);
        }
        unsigned seid = bat * 32u + (unsigned)sedge;
        unsigned pks2 = g_edges[(seid < cnt) ? seid : (cnt - 1u)];
        int si = min((int)(pks2 >> 10), NN - 1);
        int sj = min((int)(pks2 & 1023u), NN - 1);
        const float4* epp = (const float4*)(e + (size_t)(si * NN + sj) * DE + sde);
        float4 v0 = epp[0], v1 = epp[1];
        er[0] = v0.x; er[1] = v0.y; er[2] = v0.z; er[3] = v0.w;
        er[4] = v1.x; er[5] = v1.y; er[6] = v1.z; er[7] = v1.w;
    }

    // ---- weight staging ----
    {
        const float4* Wg = (const float4*)(W + (2 * FD) * HD);
        ((float4*)sWe)[tid]       = Wg[tid];
        ((float4*)sWe)[tid + 256] = Wg[tid + 256];
        const float4* Wbg = (const float4*)Wb;
#pragma unroll
        for (int k = 0; k < 4; k++)
            ((float4*)sWb)[tid + k * 256] = Wbg[tid + k * 256];
        if (tid < HD) sbb[tid] = bb[tid];
    }
    __syncthreads();

    while (have) {
        // stage e chunk into quad tile es[de][edge]
#pragma unroll
        for (int t = 0; t < 8; t++)
            es[(sde + t) * 32 + sedge] = er[t];
        asm volatile("bar.sync %0, 128;" :: "r"(barid) : "memory");

        // ---- layer a: z2t += e @ We over own tile ----
        u64* z2t = pq2;
#pragma unroll
        for (int de = 0; de < DE; de++) {
            float4 e4v = *(const float4*)(es + de * 32 + eg * 4);
            ulonglong2 w = *(const ulonglong2*)(sWe + de * HD + hoff);
            u64 zd;
            zd = pack2(e4v.x, e4v.x);
            z2t[0] = ffma2(zd, w.x, z2t[0]); z2t[1] = ffma2(zd, w.y, z2t[1]);
            zd = pack2(e4v.y, e4v.y);
            z2t[2] = ffma2(zd, w.x, z2t[2]); z2t[3] = ffma2(zd, w.y, z2t[3]);
            zd = pack2(e4v.z, e4v.z);
            z2t[4] = ffma2(zd, w.x, z2t[4]); z2t[5] = ffma2(zd, w.y, z2t[5]);
            zd = pack2(e4v.w, e4v.w);
            z2t[6] = ffma2(zd, w.x, z2t[6]); z2t[7] = ffma2(zd, w.y, z2t[7]);
        }

        // relu + store z as u64 [k2][edge]; k2 = (hoff + 2c)/2 = wq*8+hg*2+c
#pragma unroll
        for (int e4 = 0; e4 < 4; e4++) {
#pragma unroll
            for (int c = 0; c < 2; c++)
                zsu[(wq * 8 + hg * 2 + c) * 32 + eg * 4 + e4] =
                    relu2(z2t[e4 * 2 + c]);
        }
        asm volatile("bar.sync %0, 128;" :: "r"(barid) : "memory");

        // ---- layer b: m = relu(z @ Wb + bb) over own tile ----
        u64 m2[8];
        {
            ulonglong2 bv = *(const ulonglong2*)(sbb + hoff);
#pragma unroll
            for (int e4 = 0; e4 < 4; e4++) {
                m2[e4 * 2 + 0] = bv.x;
                m2[e4 * 2 + 1] = bv.y;
            }
        }
#pragma unroll 8
        for (int k2 = 0; k2 < 32; k2++) {
            ulonglong2 za = *(const ulonglong2*)(zsu + k2 * 32 + eg * 4);
            ulonglong2 zb = *(const ulonglong2*)(zsu + k2 * 32 + eg * 4 + 2);
            ulonglong2 w0 = *(const ulonglong2*)(sWb + (2 * k2 + 0) * HD + hoff);
            ulonglong2 w1 = *(const ulonglong2*)(sWb + (2 * k2 + 1) * HD + hoff);
            u64 zarr[4] = {za.x, za.y, zb.x, zb.y};
#pragma unroll
            for (int e4 = 0; e4 < 4; e4++) {
                float z0, z1; unpack2(zarr[e4], z0, z1);
                u64 zd0 = pack2(z0, z0);
                u64 zd1 = pack2(z1, z1);
                m2[e4 * 2 + 0] = ffma2(zd0, w0.x, m2[e4 * 2 + 0]);
                m2[e4 * 2 + 1] = ffma2(zd0, w0.y, m2[e4 * 2 + 1]);
                m2[e4 * 2 + 0] = ffma2(zd1, w1.x, m2[e4 * 2 + 0]);
                m2[e4 * 2 + 1] = ffma2(zd1, w1.y, m2[e4 * 2 + 1]);
            }
        }

        // relu + scatter (fused when the lane's 4 edges share row i)
#pragma unroll
        for (int c = 0; c < 8; c++) m2[c] = relu2(m2[c]);

        const unsigned ebase = bat * 32u + (unsigned)(eg * 4);
        const bool fuse = (iarr[0] == iarr[1]) & (iarr[1] == iarr[2]) &
                          (iarr[2] == iarr[3]) & (ebase + 3u < cnt);
        if (fuse) {
            u64 s0 = fadd2(fadd2(m2[0], m2[2]), fadd2(m2[4], m2[6]));
            u64 s1 = fadd2(fadd2(m2[1], m2[3]), fadd2(m2[5], m2[7]));
            float a0, a1, a2, a3;
            unpack2(s0, a0, a1); unpack2(s1, a2, a3);
            atomicAdd((float4*)(out + iarr[0] * HD + hoff),
                      make_float4(a0, a1, a2, a3));
        } else {
#pragma unroll
            for (int e4 = 0; e4 < 4; e4++) {
                if (ebase + (unsigned)e4 < cnt) {
                    float a0, a1, a2, a3;
                    unpack2(m2[e4 * 2 + 0], a0, a1);
                    unpack2(m2[e4 * 2 + 1], a2, a3);
                    atomicAdd((float4*)(out + iarr[e4] * HD + hoff),
                              make_float4(a0, a1, a2, a3));
                }
            }
        }

        // ---- advance (rare: >1 task per quad) ----
        bat += nquads;
        have = bat < nbat;
        if (have) {
            asm volatile("bar.sync %0, 128;" :: "r"(barid) : "memory");
            const unsigned eb2 = bat * 32u + (unsigned)(eg * 4);
            uint4 pks = *(const uint4*)(g_edges + eb2);
            unsigned pkarr[4] = {pks.x, pks.y, pks.z, pks.w};
#pragma unroll
            for (int e4 = 0; e4 < 4; e4++) {
                int ii = min((int)(pkarr[e4] >> 10), NN - 1);
                int jj = min((int)(pkarr[e4] & 1023u), NN - 1);
                iarr[e4] = ii;
                ulonglong2 pv = *(const ulonglong2*)(P + ii * HD + hoff);
                ulonglong2 qv = *(const ulonglong2*)(Q + jj * HD + hoff);
                pq2[e4 * 2 + 0] = fadd2(pv.x, qv.x);
                pq2[e4 * 2 + 1] = fadd2(pv.y, qv.y);
            }
            unsigned seid = bat * 32u + (unsigned)sedge;
            unsigned pks2 = g_edges[(seid < cnt) ? seid : (cnt - 1u)];
            int si = min((int)(pks2 >> 10), NN - 1);
            int sj = min((int)(pks2 & 1023u), NN - 1);
            const float4* epp = (const float4*)(e + (size_t)(si * NN + sj) * DE + sde);
            float4 v0 = epp[0], v1 = epp[1];
            er[0] = v0.x; er[1] = v0.y; er[2] = v0.z; er[3] = v0.w;
            er[4] = v1.x; er[5] = v1.y; er[6] = v1.z; er[7] = v1.w;
        }
    }
}

// out[i] = sigmoid( relu(x2_i @ W3 + b3) @ W4 + b4 ); resets g_cnt (runs last).
__global__ __launch_bounds__(128) void final_kernel(
    const float* __restrict__ x,
    const float* __restrict__ W3, const float* __restrict__ b3,
    const float* __restrict__ W4, const float* __restrict__ b4,
    float* __restrict__ out)
{
    __shared__ float sx[HD];
    __shared__ float sred[H2];
    const int i = blockIdx.x, t = threadIdx.x;
    if (i == 0 && t == 0) g_cnt = 0;
    if (t < HD) sx[t] = x[i * HD + t];
    __syncthreads();

    float h = b3[t];
#pragma unroll
    for (int k = 0; k < HD; k++)
        h = fmaf(sx[k], W3[k * H2 + t], h);
    h = fmaxf(h, 0.f);

    sred[t] = h * W4[t];
    __syncthreads();
#pragma unroll
    for (int s = 64; s > 0; s >>= 1) {
        if (t < s) sred[t] += sred[t + s];
        __syncthreads();
    }
    if (t == 0) {
        float v = sred[0] + b4[0];
        out[i] = 1.0f / (1.0f + expf(-v));
    }
}

extern "C" void kernel_launch(void* const* d_in, const int* in_sizes, int n_in,
                              void* d_out, int out_size)
{
    const float* A   = (const float*)d_in[0];
    const float* x   = (const float*)d_in[1];
    const float* e   = (const float*)d_in[2];
    const float* W1a = (const float*)d_in[3];
    const float* b1a = (const float*)d_in[4];
    const float* W1b = (const float*)d_in[5];
    const float* b1b = (const float*)d_in[6];
    const float* W2a = (const float*)d_in[7];
    const float* b2a = (const float*)d_in[8];
    const float* W2b = (const float*)d_in[9];
    const float* b2b = (const float*)d_in[10];
    const float* W3  = (const float*)d_in[11];
    const float* b3  = (const float*)d_in[12];
    const float* W4  = (const float*)d_in[13];
    const float* b4  = (const float*)d_in[14];
    float* out = (float*)d_out;

    float *P, *Q, *X1, *X2;
    cudaGetSymbolAddress((void**)&P,  g_P);
    cudaGetSymbolAddress((void**)&Q,  g_Q);
    cudaGetSymbolAddress((void**)&X1, g_X1);
    cudaGetSymbolAddress((void**)&X2, g_X2);

    const int SMEM = 12352 * 4;   // 49408 B
    cudaFuncSetAttribute(edge_kernel, cudaFuncAttributeMaxDynamicSharedMemorySize, SMEM);

    // Layer 1 (prep compacts A, computes P/Q, zeroes X1)
    prep_kernel<<<NN / 4, 256>>>(A, x, W1a, b1a, P, Q, X1);
    edge_kernel<<<EGRID, 256, SMEM>>>(e, P, Q, W1a, W1b, b1b, X1);
    // Layer 2 (no recompaction)
    prep_kernel<<<NN / 4, 256>>>(nullptr, X1, W2a, b2a, P, Q, X2);
    edge_kernel<<<EGRID, 256, SMEM>>>(e, P, Q, W2a, W2b, b2b, X2);
    // Head (also resets g_cnt)
    final_kernel<<<NN, H2>>>(X2, W3, b3, W4, b4, out);
}